// round 1
// baseline (speedup 1.0000x reference)
#include <cuda_runtime.h>
#include <mma.h>

using namespace nvcuda;

// Problem constants (fixed shapes from the reference)
#define BATCH 16
#define NTOK  8192
#define FIN   256
#define FOUT  256
#define EPSBN 1e-5f

// GEMM tiling
#define BM 128
#define BN 64
#define BK 32
#define PAD 8           // smem row pad (floats)
#define LDA (BK + PAD)  // 40
#define LDT (BN + 4)    // 68, epilogue tile leading dim

// ---- device-global scratch (no allocations allowed) ----
__device__ float g_sum  [BATCH * FOUT];
__device__ float g_sumsq[BATCH * FOUT];
__device__ float g_scale[BATCH * FOUT];
__device__ float g_shift[BATCH * FOUT];

// ---------------------------------------------------------------------------
// Kernel 0: zero the stats accumulators (graph replays need this every call)
// ---------------------------------------------------------------------------
__global__ void zero_stats_kernel() {
    int i = blockIdx.x * blockDim.x + threadIdx.x;
    if (i < BATCH * FOUT) {
        g_sum[i]   = 0.0f;
        g_sumsq[i] = 0.0f;
    }
}

// ---------------------------------------------------------------------------
// Kernel 1: y = x @ W^T + b  (tf32 wmma), fused column sum/sumsq atomics
// grid: (NTOK/BM, FOUT/BN, BATCH), block: 256 threads (8 warps, 4x2 warp grid)
// ---------------------------------------------------------------------------
__global__ __launch_bounds__(256, 2)
void gemm_stats_kernel(const float* __restrict__ x,
                       const float* __restrict__ W,
                       const float* __restrict__ bias,
                       float* __restrict__ y)
{
    // Union: mainloop uses As(128x40) + Bs(64x40) = 7680 floats.
    // Epilogue reuses as 128x68 tile = 8704 floats.
    __shared__ float smem[BM * LDT];   // 8704 floats = 34816 B
    float* As = smem;                  // [BM][LDA]
    float* Bs = smem + BM * LDA;       // [BN][LDA]

    const int b  = blockIdx.z;
    const int m0 = blockIdx.x * BM;
    const int n0 = blockIdx.y * BN;
    const int tid  = threadIdx.x;
    const int warp = tid >> 5;
    const int wm   = warp & 3;   // 0..3 -> 32-row slice
    const int wn   = warp >> 2;  // 0..1 -> 32-col slice

    const float* xb = x + (size_t)b * NTOK * FIN;

    wmma::fragment<wmma::accumulator, 16, 16, 8, float> acc[2][2];
#pragma unroll
    for (int i = 0; i < 2; i++)
#pragma unroll
        for (int j = 0; j < 2; j++)
            wmma::fill_fragment(acc[i][j], 0.0f);

    for (int k0 = 0; k0 < FIN; k0 += BK) {
        // --- load A tile: 128 rows x 32 floats = 1024 float4, 4 per thread ---
#pragma unroll
        for (int it = 0; it < 4; it++) {
            int idx = tid + it * 256;        // 0..1023
            int r   = idx >> 3;              // 8 float4 per row
            int c4  = idx & 7;
            float4 v = *reinterpret_cast<const float4*>(
                xb + (size_t)(m0 + r) * FIN + k0 + c4 * 4);
            *reinterpret_cast<float4*>(&As[r * LDA + c4 * 4]) = v;
        }
        // --- load B tile: 64 rows (Fout) x 32 floats = 512 float4, 2 per thread ---
#pragma unroll
        for (int it = 0; it < 2; it++) {
            int idx = tid + it * 256;        // 0..511
            int r   = idx >> 3;
            int c4  = idx & 7;
            float4 v = *reinterpret_cast<const float4*>(
                W + (size_t)(n0 + r) * FIN + k0 + c4 * 4);
            *reinterpret_cast<float4*>(&Bs[r * LDA + c4 * 4]) = v;
        }
        __syncthreads();

#pragma unroll
        for (int kk = 0; kk < BK; kk += 8) {
            wmma::fragment<wmma::matrix_a, 16, 16, 8, wmma::precision::tf32,
                           wmma::row_major> a_frag[2];
            wmma::fragment<wmma::matrix_b, 16, 16, 8, wmma::precision::tf32,
                           wmma::col_major> b_frag[2];
#pragma unroll
            for (int i = 0; i < 2; i++) {
                wmma::load_matrix_sync(a_frag[i],
                    &As[(wm * 32 + 16 * i) * LDA + kk], LDA);
#pragma unroll
                for (int t = 0; t < a_frag[i].num_elements; t++)
                    a_frag[i].x[t] = wmma::__float_to_tf32(a_frag[i].x[t]);
            }
#pragma unroll
            for (int j = 0; j < 2; j++) {
                // Bs is [n][k]; as col-major KxN with ld=LDA
                wmma::load_matrix_sync(b_frag[j],
                    &Bs[(wn * 32 + 16 * j) * LDA + kk], LDA);
#pragma unroll
                for (int t = 0; t < b_frag[j].num_elements; t++)
                    b_frag[j].x[t] = wmma::__float_to_tf32(b_frag[j].x[t]);
            }
#pragma unroll
            for (int i = 0; i < 2; i++)
#pragma unroll
                for (int j = 0; j < 2; j++)
                    wmma::mma_sync(acc[i][j], a_frag[i], b_frag[j], acc[i][j]);
        }
        __syncthreads();
    }

    // --- epilogue: acc -> smem tile (reuse), then bias + store + stats ---
#pragma unroll
    for (int i = 0; i < 2; i++)
#pragma unroll
        for (int j = 0; j < 2; j++)
            wmma::store_matrix_sync(
                &smem[(wm * 32 + 16 * i) * LDT + wn * 32 + 16 * j],
                acc[i][j], LDT, wmma::mem_row_major);
    __syncthreads();

    // Each thread owns column c = tid%64, rows (tid/64) + 4k, k=0..31
    const int c  = tid & 63;
    const int r0 = tid >> 6;
    const float bv = bias[n0 + c];
    float s = 0.0f, sq = 0.0f;
    float* ybase = y + ((size_t)b * NTOK + m0) * FOUT + n0 + c;
#pragma unroll
    for (int k = 0; k < 32; k++) {
        int r = r0 + 4 * k;
        float v = smem[r * LDT + c] + bv;
        ybase[(size_t)r * FOUT] = v;
        s  += v;
        sq += v * v;
    }
    atomicAdd(&g_sum  [b * FOUT + n0 + c], s);
    atomicAdd(&g_sumsq[b * FOUT + n0 + c], sq);
}

// ---------------------------------------------------------------------------
// Kernel 2: finalize stats -> per-(batch,feature) scale/shift
// ---------------------------------------------------------------------------
__global__ void finalize_stats_kernel(const float* __restrict__ gamma,
                                      const float* __restrict__ beta)
{
    int i = blockIdx.x * blockDim.x + threadIdx.x;   // b*FOUT + o
    if (i >= BATCH * FOUT) return;
    int o = i & (FOUT - 1);
    float invN = 1.0f / (float)NTOK;
    float mean = g_sum[i] * invN;
    float var  = fmaxf(g_sumsq[i] * invN - mean * mean, 0.0f);
    float sc   = gamma[o] * rsqrtf(var + EPSBN);
    g_scale[i] = sc;
    g_shift[i] = beta[o] - mean * sc;
}

// ---------------------------------------------------------------------------
// Kernel 3: in-place normalize: out = y*scale + shift   (float4 vectorized)
// ---------------------------------------------------------------------------
__global__ void normalize_kernel(float* __restrict__ y)
{
    size_t i4 = (size_t)blockIdx.x * blockDim.x + threadIdx.x;
    const size_t total4 = (size_t)BATCH * NTOK * FOUT / 4;
    if (i4 >= total4) return;
    size_t e = i4 * 4;
    int o = (int)(e & (FOUT - 1));          // aligned to 4
    int bb = (int)(e >> 21);                 // e / (8192*256)
    const float4 sc = *reinterpret_cast<const float4*>(&g_scale[bb * FOUT + o]);
    const float4 sh = *reinterpret_cast<const float4*>(&g_shift[bb * FOUT + o]);
    float4 v = reinterpret_cast<float4*>(y)[i4];
    v.x = v.x * sc.x + sh.x;
    v.y = v.y * sc.y + sh.y;
    v.z = v.z * sc.z + sh.z;
    v.w = v.w * sc.w + sh.w;
    reinterpret_cast<float4*>(y)[i4] = v;
}

// ---------------------------------------------------------------------------
extern "C" void kernel_launch(void* const* d_in, const int* in_sizes, int n_in,
                              void* d_out, int out_size)
{
    const float* x     = (const float*)d_in[0];
    const float* W     = (const float*)d_in[1];
    const float* bias  = (const float*)d_in[2];
    const float* gamma = (const float*)d_in[3];
    const float* beta  = (const float*)d_in[4];
    float* out = (float*)d_out;

    zero_stats_kernel<<<(BATCH * FOUT + 255) / 256, 256>>>();

    dim3 grid(NTOK / BM, FOUT / BN, BATCH);
    gemm_stats_kernel<<<grid, 256>>>(x, W, bias, out);

    finalize_stats_kernel<<<(BATCH * FOUT + 255) / 256, 256>>>(gamma, beta);

    size_t total4 = (size_t)BATCH * NTOK * FOUT / 4;
    normalize_kernel<<<(unsigned)((total4 + 255) / 256), 256>>>(out);
}

// round 3
// speedup vs baseline: 2.0022x; 2.0022x over previous
#include <cuda_runtime.h>
#include <cstdint>

// Problem constants
#define BATCH 16
#define NTOK  8192
#define FIN   256
#define FOUT  256
#define EPSBN 1e-5f

// GEMM tiling
#define BM 128
#define BN 128
#define BK 32
#define NCHUNK (FIN / BK)        // 8
#define STAGES 3
#define PADK 4
#define LDK (BK + PADK)          // 36 floats
#define STAGE_FLOATS ((BM + BN) * LDK)            // 9216
#define SMEM_ALLOC (STAGES * STAGE_FLOATS * 4)    // 110592 B

// device-global scratch (no allocations allowed)
__device__ float g_sum  [BATCH * FOUT];
__device__ float g_sumsq[BATCH * FOUT];
__device__ float g_scale[BATCH * FOUT];
__device__ float g_shift[BATCH * FOUT];

// ---------------------------------------------------------------------------
__device__ __forceinline__ uint32_t s2u(const void* p) {
    uint32_t a;
    asm("{ .reg .u64 t; cvta.to.shared.u64 t, %1; cvt.u32.u64 %0, t; }"
        : "=r"(a) : "l"(p));
    return a;
}
__device__ __forceinline__ void cp16(uint32_t saddr, const void* g) {
    asm volatile("cp.async.cg.shared.global [%0], [%1], 16;"
                 :: "r"(saddr), "l"(g));
}
__device__ __forceinline__ void mma_tf32(float* c, const uint32_t* a,
                                         const uint32_t* b) {
    asm volatile(
        "mma.sync.aligned.m16n8k8.row.col.f32.tf32.tf32.f32 "
        "{%0,%1,%2,%3}, {%4,%5,%6,%7}, {%8,%9}, {%0,%1,%2,%3};"
        : "+f"(c[0]), "+f"(c[1]), "+f"(c[2]), "+f"(c[3])
        : "r"(a[0]), "r"(a[1]), "r"(a[2]), "r"(a[3]), "r"(b[0]), "r"(b[1]));
}

// ---------------------------------------------------------------------------
// Kernel 0: zero stats accumulators
// ---------------------------------------------------------------------------
__global__ void zero_stats_kernel() {
    int i = blockIdx.x * blockDim.x + threadIdx.x;
    if (i < BATCH * FOUT) { g_sum[i] = 0.0f; g_sumsq[i] = 0.0f; }
}

// ---------------------------------------------------------------------------
// Kernel 1: mma.sync tf32 GEMM  y = x @ W^T + b, fused column stats
// grid = BATCH * 64 * 2  (n-tile fastest for L2 reuse of x), block = 256
// ---------------------------------------------------------------------------
__global__ __launch_bounds__(256, 2)
void gemm_mma_kernel(const float* __restrict__ x,
                     const float* __restrict__ W,
                     const float* __restrict__ bias,
                     float* __restrict__ y)
{
    extern __shared__ float smem[];
    const uint32_t smem_u = s2u(smem);

    const int tid  = threadIdx.x;
    const int wid  = tid >> 5;
    const int lane = tid & 31;
    const int g    = lane >> 2;          // 0..7
    const int t    = lane & 3;           // 0..3

    const int bx = blockIdx.x;
    const int nt = bx & 1;
    const int mt = (bx >> 1) & 63;
    const int b  = bx >> 7;
    const int m0 = mt * BM;
    const int n0 = nt * BN;

    const float* xb = x + ((size_t)b * NTOK + m0) * FIN;
    const float* Wb = W + (size_t)n0 * FIN;

    const int warp_m = wid & 3;          // 0..3 -> 32-row slice
    const int warp_n = wid >> 2;         // 0..1 -> 64-col slice

    float acc[2][8][4];
#pragma unroll
    for (int mi = 0; mi < 2; mi++)
#pragma unroll
        for (int ni = 0; ni < 8; ni++)
#pragma unroll
            for (int i = 0; i < 4; i++) acc[mi][ni][i] = 0.0f;

    // stage loader: A[128][BK] + B[128][BK] as 16B cp.async granules
    const int lr = tid >> 3;        // 0..31  (row base step 32 over 4 iters)
    const int lg = tid & 7;         // granule within row
    auto load_stage = [&](int c, int s) {
        const uint32_t abase = smem_u + (uint32_t)(s * STAGE_FLOATS) * 4u;
        const uint32_t bbase = abase + (uint32_t)(BM * LDK) * 4u;
        const int k0 = c * BK;
#pragma unroll
        for (int i = 0; i < 4; i++) {
            int r = lr + i * 32;
            cp16(abase + (uint32_t)(r * LDK + lg * 4) * 4u,
                 xb + (size_t)r * FIN + k0 + lg * 4);
        }
#pragma unroll
        for (int i = 0; i < 4; i++) {
            int r = lr + i * 32;
            cp16(bbase + (uint32_t)(r * LDK + lg * 4) * 4u,
                 Wb + (size_t)r * FIN + k0 + lg * 4);
        }
    };

    // prologue: STAGES-1 stages in flight
#pragma unroll
    for (int s = 0; s < STAGES - 1; s++) {
        load_stage(s, s);
        asm volatile("cp.async.commit_group;" ::: "memory");
    }

    // mainloop
    for (int c = 0; c < NCHUNK; c++) {
        asm volatile("cp.async.wait_group %0;" :: "n"(STAGES - 2) : "memory");
        __syncthreads();

        if (c + STAGES - 1 < NCHUNK)
            load_stage(c + STAGES - 1, (c + STAGES - 1) % STAGES);
        asm volatile("cp.async.commit_group;" ::: "memory");

        const float* As = smem + (c % STAGES) * STAGE_FLOATS
                          + (warp_m * 32) * LDK;
        const float* Bs = smem + (c % STAGES) * STAGE_FLOATS + BM * LDK
                          + (warp_n * 64) * LDK;

#pragma unroll
        for (int ks = 0; ks < 4; ks++) {
            const int kk = ks * 8;
            uint32_t af[2][4];
#pragma unroll
            for (int mi = 0; mi < 2; mi++) {
                int r = mi * 16 + g;
                af[mi][0] = __float_as_uint(As[ r      * LDK + kk + t    ]);
                af[mi][1] = __float_as_uint(As[(r + 8) * LDK + kk + t    ]);
                af[mi][2] = __float_as_uint(As[ r      * LDK + kk + t + 4]);
                af[mi][3] = __float_as_uint(As[(r + 8) * LDK + kk + t + 4]);
            }
            uint32_t bf[8][2];
#pragma unroll
            for (int ni = 0; ni < 8; ni++) {
                int n = ni * 8 + g;
                bf[ni][0] = __float_as_uint(Bs[n * LDK + kk + t    ]);
                bf[ni][1] = __float_as_uint(Bs[n * LDK + kk + t + 4]);
            }
#pragma unroll
            for (int mi = 0; mi < 2; mi++)
#pragma unroll
                for (int ni = 0; ni < 8; ni++)
                    mma_tf32(acc[mi][ni], af[mi], bf[ni]);
        }
    }

    // ---------------- epilogue: bias + y store + column stats ----------------
    __syncthreads();
    float* psum = smem;            // [128]
    float* psq  = smem + 128;      // [128]
    if (tid < 128) { psum[tid] = 0.0f; psq[tid] = 0.0f; }
    __syncthreads();

    float* ybase = y + ((size_t)b * NTOK + m0) * FOUT + n0;
    const int rA0 = warp_m * 32 + g;     // mi*16 added per frag

#pragma unroll
    for (int ni = 0; ni < 8; ni++) {
        const int cc = warp_n * 64 + ni * 8 + 2 * t;
        const float b0v = __ldg(&bias[n0 + cc]);
        const float b1v = __ldg(&bias[n0 + cc + 1]);
        float s0 = 0.f, s1 = 0.f, q0 = 0.f, q1 = 0.f;
#pragma unroll
        for (int mi = 0; mi < 2; mi++) {
            int r = rA0 + mi * 16;
            float v0 = acc[mi][ni][0] + b0v;
            float v1 = acc[mi][ni][1] + b1v;
            float v2 = acc[mi][ni][2] + b0v;
            float v3 = acc[mi][ni][3] + b1v;
            *(float2*)(ybase + (size_t)r * FOUT + cc)       = make_float2(v0, v1);
            *(float2*)(ybase + (size_t)(r + 8) * FOUT + cc) = make_float2(v2, v3);
            s0 += v0 + v2;  s1 += v1 + v3;
            q0 += v0 * v0 + v2 * v2;
            q1 += v1 * v1 + v3 * v3;
        }
        // reduce over the 8 row-groups (lanes differing in bits [2:4])
#pragma unroll
        for (int m = 4; m <= 16; m <<= 1) {
            s0 += __shfl_xor_sync(0xFFFFFFFF, s0, m);
            s1 += __shfl_xor_sync(0xFFFFFFFF, s1, m);
            q0 += __shfl_xor_sync(0xFFFFFFFF, q0, m);
            q1 += __shfl_xor_sync(0xFFFFFFFF, q1, m);
        }
        if (lane < 4) {                       // g == 0 lanes hold totals
            atomicAdd(&psum[cc], s0);  atomicAdd(&psum[cc + 1], s1);
            atomicAdd(&psq [cc], q0);  atomicAdd(&psq [cc + 1], q1);
        }
    }
    __syncthreads();
    if (tid < 128) {
        atomicAdd(&g_sum  [b * FOUT + n0 + tid], psum[tid]);
        atomicAdd(&g_sumsq[b * FOUT + n0 + tid], psq [tid]);
    }
}

// ---------------------------------------------------------------------------
// Kernel 2: finalize stats -> per-(batch,feature) scale/shift
// ---------------------------------------------------------------------------
__global__ void finalize_stats_kernel(const float* __restrict__ gamma,
                                      const float* __restrict__ beta)
{
    int i = blockIdx.x * blockDim.x + threadIdx.x;
    if (i >= BATCH * FOUT) return;
    int o = i & (FOUT - 1);
    float invN = 1.0f / (float)NTOK;
    float mean = g_sum[i] * invN;
    float var  = fmaxf(g_sumsq[i] * invN - mean * mean, 0.0f);
    float sc   = gamma[o] * rsqrtf(var + EPSBN);
    g_scale[i] = sc;
    g_shift[i] = beta[o] - mean * sc;
}

// ---------------------------------------------------------------------------
// Kernel 3: in-place normalize (float4)
// ---------------------------------------------------------------------------
__global__ void normalize_kernel(float* __restrict__ y)
{
    size_t i4 = (size_t)blockIdx.x * blockDim.x + threadIdx.x;
    const size_t total4 = (size_t)BATCH * NTOK * FOUT / 4;
    if (i4 >= total4) return;
    size_t e = i4 * 4;
    int o  = (int)(e & (FOUT - 1));
    int bb = (int)(e >> 21);
    const float4 sc = *reinterpret_cast<const float4*>(&g_scale[bb * FOUT + o]);
    const float4 sh = *reinterpret_cast<const float4*>(&g_shift[bb * FOUT + o]);
    float4 v = reinterpret_cast<float4*>(y)[i4];
    v.x = v.x * sc.x + sh.x;
    v.y = v.y * sc.y + sh.y;
    v.z = v.z * sc.z + sh.z;
    v.w = v.w * sc.w + sh.w;
    reinterpret_cast<float4*>(y)[i4] = v;
}

// ---------------------------------------------------------------------------
extern "C" void kernel_launch(void* const* d_in, const int* in_sizes, int n_in,
                              void* d_out, int out_size)
{
    const float* x     = (const float*)d_in[0];
    const float* W     = (const float*)d_in[1];
    const float* bias  = (const float*)d_in[2];
    const float* gamma = (const float*)d_in[3];
    const float* beta  = (const float*)d_in[4];
    float* out = (float*)d_out;

    cudaFuncSetAttribute(gemm_mma_kernel,
                         cudaFuncAttributeMaxDynamicSharedMemorySize,
                         SMEM_ALLOC);

    zero_stats_kernel<<<(BATCH * FOUT + 255) / 256, 256>>>();

    gemm_mma_kernel<<<BATCH * 64 * 2, 256, SMEM_ALLOC>>>(x, W, bias, out);

    finalize_stats_kernel<<<(BATCH * FOUT + 255) / 256, 256>>>(gamma, beta);

    size_t total4 = (size_t)BATCH * NTOK * FOUT / 4;
    normalize_kernel<<<(unsigned)((total4 + 255) / 256), 256>>>(out);
}